// round 15
// baseline (speedup 1.0000x reference)
#include <cuda_runtime.h>
#include <cstdint>

#define NVOX (64*64*64)        // 262144 voxels
#define NQ   (NVOX/4)          // 65536 float4 per (b,k) slab
#define BKN 28                 // 4 batches * 7 moving parts
#define CHUNKS 32              // partial-reduction chunks per (b,k)
#define NBLOCKS (BKN * CHUNKS) // 896 reduce blocks
#define RED_THREADS 256
#define APPLY_THREADS 512      // 4 blocks/SM => 64 warps/SM (max occupancy)
#define APPLY_SMEM (7 * APPLY_THREADS * 16)   // 57344 B dynamic

// Scratch (no allocations allowed)
__device__ float    g_partial[NBLOCKS * 4];
__device__ float    g_coef[BKN * 12];     // [0..8]=M=R-I row-major, [9..11]=d
__device__ unsigned g_count = 0;          // self-resets every launch

// ---------------- helpers ----------------
__device__ __forceinline__ uint32_t smem_u32(const void* p) {
    uint32_t a;
    asm("{ .reg .u64 t; cvta.to.shared.u64 t, %1; cvt.u32.u64 %0, t; }"
        : "=r"(a) : "l"(p));
    return a;
}
__device__ __forceinline__ void cp_async16(uint32_t dst_smem, const void* src) {
    asm volatile("cp.async.cg.shared.global [%0], [%1], 16;"
                 :: "r"(dst_smem), "l"(src) : "memory");
}
__device__ __forceinline__ void pdl_trigger() {          // allow dependent grid launch
    asm volatile("griddepcontrol.launch_dependents;");
}
__device__ __forceinline__ void pdl_wait() {             // wait for primary grid done
    asm volatile("griddepcontrol.wait;" ::: "memory");
}

// ---------------------------------------------------------------------------
// Pass 1 (primary): per-(b,k) weighted sums (sum m, sum m*gx, m*gy, m*gz).
// Exact R10 champion shape: 896 blocks x 256 thr, 8 x 16B cp.async/thread.
// LAST block folds partials -> coefficients: M = R - I, d = p + t - R p.
// ---------------------------------------------------------------------------
__global__ void __launch_bounds__(RED_THREADS, 6)
reduce_k(const float* __restrict__ mask, const float* __restrict__ grids,
         const float* __restrict__ trans_vec, const float* __restrict__ rot_mat)
{
    const int bk    = blockIdx.x >> 5;     // / CHUNKS
    const int chunk = blockIdx.x & 31;     // % CHUNKS
    const int b = bk / 7, k = bk % 7;
    const int tid = threadIdx.x;

    __shared__ __align__(16) float4 buf[2048];      // 32 KB chunk
    __shared__ float ax[64], ay[64], az[64];
    __shared__ float red[8][4];
    __shared__ float fold[BKN][4];
    __shared__ bool  is_last;

    const float4* m4 = (const float4*)(mask + ((size_t)(b * 8 + k)) * NVOX)
                       + (size_t)chunk * 2048;

    // ---- 8 async copies per thread, all in flight immediately ----
#pragma unroll
    for (int t = 0; t < 8; ++t)
        cp_async16(smem_u32(&buf[t * RED_THREADS + tid]), &m4[t * RED_THREADS + tid]);
    asm volatile("cp.async.commit_group;" ::: "memory");

    pdl_trigger();                                   // let apply_k start prefetch

    if (tid < 64) {
        ax[tid] = grids[tid << 12];                 // gx[i,0,0]
        ay[tid] = grids[NVOX + (tid << 6)];         // gy[0,j,0]
        az[tid] = grids[2 * NVOX + tid];            // gz[0,0,k]
    }
    __syncthreads();                                 // axes ready

    asm volatile("cp.async.wait_group 0;" ::: "memory");  // own 16B slots ready

    const int vbase = chunk * (NVOX / CHUNKS);
    float s0 = 0.f, sx = 0.f, sy = 0.f, sz = 0.f;
#pragma unroll
    for (int t = 0; t < 8; ++t) {
        const int idx4 = t * RED_THREADS + tid;
        const float4 m = buf[idx4];                 // conflict-free LDS.128
        const int v  = vbase + (idx4 << 2);
        const int i  = v >> 12;
        const int j  = (v >> 6) & 63;
        const int kk = v & 63;
        const float ms = (m.x + m.y) + (m.z + m.w);
        s0 += ms;
        sx = fmaf(ax[i], ms, sx);
        sy = fmaf(ay[j], ms, sy);
        sz = fmaf(az[kk],     m.x,
             fmaf(az[kk + 1], m.y,
             fmaf(az[kk + 2], m.z,
             fmaf(az[kk + 3], m.w, sz))));
    }

    // warp tree reduce (deterministic)
#pragma unroll
    for (int off = 16; off; off >>= 1) {
        s0 += __shfl_down_sync(0xFFFFFFFFu, s0, off);
        sx += __shfl_down_sync(0xFFFFFFFFu, sx, off);
        sy += __shfl_down_sync(0xFFFFFFFFu, sy, off);
        sz += __shfl_down_sync(0xFFFFFFFFu, sz, off);
    }
    const int w = tid >> 5, l = tid & 31;
    if (l == 0) { red[w][0] = s0; red[w][1] = sx; red[w][2] = sy; red[w][3] = sz; }
    __syncthreads();
    if (tid == 0) {
        float r0 = 0.f, r1 = 0.f, r2 = 0.f, r3 = 0.f;
#pragma unroll
        for (int i = 0; i < 8; ++i) {
            r0 += red[i][0]; r1 += red[i][1]; r2 += red[i][2]; r3 += red[i][3];
        }
        float* p = g_partial + blockIdx.x * 4;
        p[0] = r0; p[1] = r1; p[2] = r2; p[3] = r3;
        __threadfence();                                // publish partial
        const unsigned arrived = atomicAdd(&g_count, 1u);
        is_last = (arrived == NBLOCKS - 1);
        if (is_last) g_count = 0;                       // reset for next replay
    }
    __syncthreads();
    if (!is_last) return;

    // -------- last block: fold partials -> coefficients (L2-hot) --------
    if (tid < BKN * 4) {                 // 112 threads: one (bk, component) each
        const int fbk  = tid >> 2;
        const int comp = tid & 3;
        const float* p = g_partial + (fbk * CHUNKS) * 4 + comp;
        float s = 0.f;
#pragma unroll
        for (int c = 0; c < CHUNKS; ++c)
            s += __ldcg(p + c * 4);
        fold[fbk][comp] = s;
    }
    __syncthreads();
    if (tid < BKN) {
        const float inv = 1.f / fold[tid][0];
        const float pv[3] = { fold[tid][1] * inv, fold[tid][2] * inv, fold[tid][3] * inv };
        const float* R = rot_mat   + tid * 9;
        const float* t = trans_vec + tid * 3;
        float* c = g_coef + tid * 12;
#pragma unroll
        for (int r = 0; r < 3; ++r) {
            const float Rp = R[r * 3] * pv[0] + R[r * 3 + 1] * pv[1] + R[r * 3 + 2] * pv[2];
            c[r * 3 + 0] = R[r * 3 + 0] - (r == 0 ? 1.f : 0.f);
            c[r * 3 + 1] = R[r * 3 + 1] - (r == 1 ? 1.f : 0.f);
            c[r * 3 + 2] = R[r * 3 + 2] - (r == 2 ? 1.f : 0.f);
            c[9 + r]     = pv[r] + t[r] - Rp;
        }
    }
    // g_coef visible to apply_k: griddepcontrol.wait orders on full kernel completion
}

// ---------------------------------------------------------------------------
// Pass 2 (secondary, PDL): 512 threads, 4 blocks/SM (64 warps/SM — max occ).
// Prefetch 7 x 16B mask slices + axes BEFORE the dependency wait; read
// coefficients after. Per-voxel arithmetic identical to R10 champion.
// motion[b,c,v] = sum_{k<7} mask[b,k,v] * (M_bk[c,:].g_v + d_bk[c]).
// ---------------------------------------------------------------------------
__global__ void __launch_bounds__(APPLY_THREADS, 4)
apply_k(const float* __restrict__ mask, const float* __restrict__ grids,
        float* __restrict__ out)
{
    extern __shared__ __align__(16) float4 sbuf[];   // 7 * 512 f4 = 56 KB
    __shared__ float cf[84];
    __shared__ float ay[64], az[64];

    const int blocksPerB = NQ / APPLY_THREADS;   // 128
    const int b   = blockIdx.x / blocksPerB;
    const int blk = blockIdx.x % blocksPerB;
    const int tid = threadIdx.x;

    const int idx4 = blk * APPLY_THREADS + tid;
    const float4* mb = (const float4*)mask + ((size_t)b * 8) * NQ + idx4;

    // ---- prefetch: independent of primary's results ----
#pragma unroll
    for (int k = 0; k < 7; ++k)
        cp_async16(smem_u32(&sbuf[k * APPLY_THREADS + tid]), &mb[(size_t)k * NQ]);
    asm volatile("cp.async.commit_group;" ::: "memory");

    if (tid < 64) {
        ay[tid] = grids[NVOX + (tid << 6)];
        az[tid] = grids[2 * NVOX + tid];
    }
    // 512 f4 = half an x-plane (1024 f4/plane) -> gx still block-constant
    const float gx = grids[(size_t)(blk >> 1) << 12];

    pdl_wait();                                      // primary grid fully done

    if (tid < 84) cf[tid] = g_coef[b * 84 + tid];    // coefficients now final
    __syncthreads();                                 // cf + axes ready

    asm volatile("cp.async.wait_group 0;" ::: "memory");  // own 16B slots ready

    const int v  = idx4 << 2;
    const int j  = (v >> 6) & 63;
    const int kk = v & 63;
    const float gy = ay[j];
    const float gz[4] = { az[kk], az[kk + 1], az[kk + 2], az[kk + 3] };

    float mot[3][4] = {};
#pragma unroll
    for (int k = 0; k < 7; ++k) {
        const float4 m = sbuf[k * APPLY_THREADS + tid];
        const float mvv[4] = { m.x, m.y, m.z, m.w };
        const float* c = cf + k * 12;
#pragma unroll
        for (int cc = 0; cc < 3; ++cc) {
            const float m2   = c[cc * 3 + 2];
            const float base = fmaf(c[cc * 3], gx, fmaf(c[cc * 3 + 1], gy, c[9 + cc]));
#pragma unroll
            for (int t = 0; t < 4; ++t)
                mot[cc][t] = fmaf(mvv[t], fmaf(m2, gz[t], base), mot[cc][t]);
        }
    }

    float4* o4 = (float4*)out;
#pragma unroll
    for (int cc = 0; cc < 3; ++cc) {
        float4 o = { mot[cc][0], mot[cc][1], mot[cc][2], mot[cc][3] };
        o4[((size_t)b * 3 + cc) * NQ + idx4] = o;
    }
}

// ---------------------------------------------------------------------------
extern "C" void kernel_launch(void* const* d_in, const int* in_sizes, int n_in,
                              void* d_out, int out_size)
{
    const float* mask = nullptr;
    const float* tv   = nullptr;
    const float* rm   = nullptr;
    const float* gr   = nullptr;
    for (int i = 0; i < n_in; ++i) {
        switch (in_sizes[i]) {
            case 8388608: mask = (const float*)d_in[i]; break;   // (4,8,64,64,64)
            case 84:      tv   = (const float*)d_in[i]; break;   // (4,7,3)
            case 252:     rm   = (const float*)d_in[i]; break;   // (4,7,3,3)
            case 786432:  gr   = (const float*)d_in[i]; break;   // (3,64,64,64)
        }
    }

    static bool attr_set = false;
    if (!attr_set) {
        cudaFuncSetAttribute(apply_k, cudaFuncAttributeMaxDynamicSharedMemorySize,
                             APPLY_SMEM);
        attr_set = true;
    }

    // Primary
    reduce_k<<<NBLOCKS, RED_THREADS>>>(mask, gr, tv, rm);

    // Secondary with Programmatic Dependent Launch: begins its prefetch while
    // reduce_k drains; griddepcontrol.wait guards the coefficient read.
    cudaLaunchConfig_t cfg = {};
    cfg.gridDim  = dim3(4 * (NQ / APPLY_THREADS), 1, 1);   // 512 blocks
    cfg.blockDim = dim3(APPLY_THREADS, 1, 1);
    cfg.dynamicSmemBytes = APPLY_SMEM;
    cfg.stream = 0;                                  // legacy default stream (captured)
    cudaLaunchAttribute attr[1];
    attr[0].id = cudaLaunchAttributeProgrammaticStreamSerialization;
    attr[0].val.programmaticStreamSerializationAllowed = 1;
    cfg.attrs = attr;
    cfg.numAttrs = 1;
    cudaLaunchKernelEx(&cfg, apply_k, mask, gr, (float*)d_out);
}

// round 16
// speedup vs baseline: 1.2429x; 1.2429x over previous
#include <cuda_runtime.h>
#include <cstdint>

#define NVOX (64*64*64)        // 262144 voxels
#define NQ   (NVOX/4)          // 65536 float4 per (b,k) slab
#define BKN 28                 // 4 batches * 7 moving parts
#define CHUNKS 32              // partial-reduction chunks per (b,k)
#define NBLOCKS (BKN * CHUNKS) // 896 reduce blocks
#define RED_THREADS 256
#define APPLY_THREADS 256

// Scratch (no allocations allowed)
__device__ float    g_partial[NBLOCKS * 4];
__device__ float    g_coef[BKN * 12];     // [0..8]=M=R-I row-major, [9..11]=d
__device__ unsigned g_count = 0;          // self-resets every launch

// ---------------- helpers ----------------
__device__ __forceinline__ uint32_t smem_u32(const void* p) {
    uint32_t a;
    asm("{ .reg .u64 t; cvta.to.shared.u64 t, %1; cvt.u32.u64 %0, t; }"
        : "=r"(a) : "l"(p));
    return a;
}
__device__ __forceinline__ void cp_async16(uint32_t dst_smem, const void* src) {
    asm volatile("cp.async.cg.shared.global [%0], [%1], 16;"
                 :: "r"(dst_smem), "l"(src) : "memory");
}
__device__ __forceinline__ void pdl_trigger() {          // allow dependent grid launch
    asm volatile("griddepcontrol.launch_dependents;");
}
__device__ __forceinline__ void pdl_wait() {             // wait for primary grid done
    asm volatile("griddepcontrol.wait;" ::: "memory");
}

// ---------------------------------------------------------------------------
// Pass 1 (primary): per-(b,k) weighted sums (sum m, sum m*gx, m*gy, m*gz).
// Byte-for-byte the R10 champion. LAST block folds partials -> coefficients:
// M = R - I, d = p + t - R p.
// ---------------------------------------------------------------------------
__global__ void __launch_bounds__(RED_THREADS, 6)
reduce_k(const float* __restrict__ mask, const float* __restrict__ grids,
         const float* __restrict__ trans_vec, const float* __restrict__ rot_mat)
{
    const int bk    = blockIdx.x >> 5;     // / CHUNKS
    const int chunk = blockIdx.x & 31;     // % CHUNKS
    const int b = bk / 7, k = bk % 7;
    const int tid = threadIdx.x;

    __shared__ __align__(16) float4 buf[2048];      // 32 KB chunk
    __shared__ float ax[64], ay[64], az[64];
    __shared__ float red[8][4];
    __shared__ float fold[BKN][4];
    __shared__ bool  is_last;

    const float4* m4 = (const float4*)(mask + ((size_t)(b * 8 + k)) * NVOX)
                       + (size_t)chunk * 2048;

    // ---- 8 async copies per thread, all in flight immediately ----
#pragma unroll
    for (int t = 0; t < 8; ++t)
        cp_async16(smem_u32(&buf[t * RED_THREADS + tid]), &m4[t * RED_THREADS + tid]);
    asm volatile("cp.async.commit_group;" ::: "memory");

    pdl_trigger();                                   // let apply_k start prefetch

    if (tid < 64) {
        ax[tid] = grids[tid << 12];                 // gx[i,0,0]
        ay[tid] = grids[NVOX + (tid << 6)];         // gy[0,j,0]
        az[tid] = grids[2 * NVOX + tid];            // gz[0,0,k]
    }
    __syncthreads();                                 // axes ready

    asm volatile("cp.async.wait_group 0;" ::: "memory");  // own 16B slots ready

    const int vbase = chunk * (NVOX / CHUNKS);
    float s0 = 0.f, sx = 0.f, sy = 0.f, sz = 0.f;
#pragma unroll
    for (int t = 0; t < 8; ++t) {
        const int idx4 = t * RED_THREADS + tid;
        const float4 m = buf[idx4];                 // conflict-free LDS.128
        const int v  = vbase + (idx4 << 2);
        const int i  = v >> 12;
        const int j  = (v >> 6) & 63;
        const int kk = v & 63;
        const float ms = (m.x + m.y) + (m.z + m.w);
        s0 += ms;
        sx = fmaf(ax[i], ms, sx);
        sy = fmaf(ay[j], ms, sy);
        sz = fmaf(az[kk],     m.x,
             fmaf(az[kk + 1], m.y,
             fmaf(az[kk + 2], m.z,
             fmaf(az[kk + 3], m.w, sz))));
    }

    // warp tree reduce (deterministic)
#pragma unroll
    for (int off = 16; off; off >>= 1) {
        s0 += __shfl_down_sync(0xFFFFFFFFu, s0, off);
        sx += __shfl_down_sync(0xFFFFFFFFu, sx, off);
        sy += __shfl_down_sync(0xFFFFFFFFu, sy, off);
        sz += __shfl_down_sync(0xFFFFFFFFu, sz, off);
    }
    const int w = tid >> 5, l = tid & 31;
    if (l == 0) { red[w][0] = s0; red[w][1] = sx; red[w][2] = sy; red[w][3] = sz; }
    __syncthreads();
    if (tid == 0) {
        float r0 = 0.f, r1 = 0.f, r2 = 0.f, r3 = 0.f;
#pragma unroll
        for (int i = 0; i < 8; ++i) {
            r0 += red[i][0]; r1 += red[i][1]; r2 += red[i][2]; r3 += red[i][3];
        }
        float* p = g_partial + blockIdx.x * 4;
        p[0] = r0; p[1] = r1; p[2] = r2; p[3] = r3;
        __threadfence();                                // publish partial
        const unsigned arrived = atomicAdd(&g_count, 1u);
        is_last = (arrived == NBLOCKS - 1);
        if (is_last) g_count = 0;                       // reset for next replay
    }
    __syncthreads();
    if (!is_last) return;

    // -------- last block: fold partials -> coefficients (L2-hot) --------
    if (tid < BKN * 4) {                 // 112 threads: one (bk, component) each
        const int fbk  = tid >> 2;
        const int comp = tid & 3;
        const float* p = g_partial + (fbk * CHUNKS) * 4 + comp;
        float s = 0.f;
#pragma unroll
        for (int c = 0; c < CHUNKS; ++c)
            s += __ldcg(p + c * 4);
        fold[fbk][comp] = s;
    }
    __syncthreads();
    if (tid < BKN) {
        const float inv = 1.f / fold[tid][0];
        const float pv[3] = { fold[tid][1] * inv, fold[tid][2] * inv, fold[tid][3] * inv };
        const float* R = rot_mat   + tid * 9;
        const float* t = trans_vec + tid * 3;
        float* c = g_coef + tid * 12;
#pragma unroll
        for (int r = 0; r < 3; ++r) {
            const float Rp = R[r * 3] * pv[0] + R[r * 3 + 1] * pv[1] + R[r * 3 + 2] * pv[2];
            c[r * 3 + 0] = R[r * 3 + 0] - (r == 0 ? 1.f : 0.f);
            c[r * 3 + 1] = R[r * 3 + 1] - (r == 1 ? 1.f : 0.f);
            c[r * 3 + 2] = R[r * 3 + 2] - (r == 2 ? 1.f : 0.f);
            c[9 + r]     = pv[r] + t[r] - Rp;
        }
    }
    // g_coef visible to apply_k: griddepcontrol.wait orders on full kernel completion
}

// ---------------------------------------------------------------------------
// Pass 2 (secondary, PDL): split motion = Sum m*(M g) + Sum m*d.
// M = R - I comes straight from rot_mat (an INPUT), so the whole M-part —
// mask prefetch + all heavy FMAs — runs BEFORE pdl_wait, overlapped with the
// primary. Post-wait tail: read 21 d values, 84 FMAs, 3 stores.
// ---------------------------------------------------------------------------
__global__ void __launch_bounds__(APPLY_THREADS, 6)
apply_k(const float* __restrict__ mask, const float* __restrict__ grids,
        const float* __restrict__ rot_mat, float* __restrict__ out)
{
    const int blocksPerB = NQ / APPLY_THREADS;   // 256
    const int b   = blockIdx.x / blocksPerB;
    const int blk = blockIdx.x % blocksPerB;
    const int tid = threadIdx.x;

    __shared__ __align__(16) float4 sbuf[7 * 256];   // 28 KB: 7 mask slices
    __shared__ float cfM[63];          // M_k = R_k - I, [k*9 + r*3 + c]
    __shared__ float sd[21];           // d_k[cc], [k*3 + cc]
    __shared__ float ay[64], az[64];

    const int idx4 = blk * APPLY_THREADS + tid;
    const float4* mb = (const float4*)mask + ((size_t)b * 8) * NQ + idx4;

    // ---- prefetch masks (independent of primary) ----
#pragma unroll
    for (int k = 0; k < 7; ++k)
        cp_async16(smem_u32(&sbuf[k * 256 + tid]), &mb[(size_t)k * NQ]);
    asm volatile("cp.async.commit_group;" ::: "memory");

    if (tid < 64) {
        ay[tid] = grids[NVOX + (tid << 6)];
        az[tid] = grids[2 * NVOX + tid];
    }
    if (tid < 63) {                    // M from the raw input — no wait needed
        const int rc = tid % 9;
        const float r = __ldg(&rot_mat[(size_t)b * 63 + tid]);
        cfM[tid] = r - ((rc == 0 || rc == 4 || rc == 8) ? 1.f : 0.f);
    }
    const float gx = grids[(size_t)(blk >> 2) << 12];   // block-constant x-plane
    __syncthreads();                                    // cfM + axes ready

    asm volatile("cp.async.wait_group 0;" ::: "memory");  // own 16B slots ready

    const int v  = idx4 << 2;
    const int j  = (v >> 6) & 63;
    const int kk = v & 63;
    const float gy = ay[j];
    const float gz[4] = { az[kk], az[kk + 1], az[kk + 2], az[kk + 3] };

    // ---- M-part: the heavy FMA work, fully overlapped with the primary ----
    float mot[3][4] = {};
#pragma unroll
    for (int k = 0; k < 7; ++k) {
        const float4 m = sbuf[k * 256 + tid];
        const float mvv[4] = { m.x, m.y, m.z, m.w };
        const float* M = cfM + k * 9;
#pragma unroll
        for (int cc = 0; cc < 3; ++cc) {
            const float m2   = M[cc * 3 + 2];
            const float base = fmaf(M[cc * 3], gx, M[cc * 3 + 1] * gy);
#pragma unroll
            for (int t = 0; t < 4; ++t)
                mot[cc][t] = fmaf(mvv[t], fmaf(m2, gz[t], base), mot[cc][t]);
        }
    }

    // ---- d-part: the only work that needs the reduction ----
    pdl_wait();                                      // primary grid fully done
    if (tid < 21)
        sd[tid] = g_coef[b * 84 + (tid / 3) * 12 + 9 + (tid % 3)];
    __syncthreads();                                 // sd ready

#pragma unroll
    for (int k = 0; k < 7; ++k) {
        const float4 m = sbuf[k * 256 + tid];
        const float mvv[4] = { m.x, m.y, m.z, m.w };
#pragma unroll
        for (int cc = 0; cc < 3; ++cc) {
            const float d = sd[k * 3 + cc];
#pragma unroll
            for (int t = 0; t < 4; ++t)
                mot[cc][t] = fmaf(mvv[t], d, mot[cc][t]);
        }
    }

    float4* o4 = (float4*)out;
#pragma unroll
    for (int cc = 0; cc < 3; ++cc) {
        float4 o = { mot[cc][0], mot[cc][1], mot[cc][2], mot[cc][3] };
        o4[((size_t)b * 3 + cc) * NQ + idx4] = o;
    }
}

// ---------------------------------------------------------------------------
extern "C" void kernel_launch(void* const* d_in, const int* in_sizes, int n_in,
                              void* d_out, int out_size)
{
    const float* mask = nullptr;
    const float* tv   = nullptr;
    const float* rm   = nullptr;
    const float* gr   = nullptr;
    for (int i = 0; i < n_in; ++i) {
        switch (in_sizes[i]) {
            case 8388608: mask = (const float*)d_in[i]; break;   // (4,8,64,64,64)
            case 84:      tv   = (const float*)d_in[i]; break;   // (4,7,3)
            case 252:     rm   = (const float*)d_in[i]; break;   // (4,7,3,3)
            case 786432:  gr   = (const float*)d_in[i]; break;   // (3,64,64,64)
        }
    }

    // Primary
    reduce_k<<<NBLOCKS, RED_THREADS>>>(mask, gr, tv, rm);

    // Secondary with Programmatic Dependent Launch: runs its prefetch AND the
    // M-part compute while reduce_k drains; griddepcontrol.wait guards only
    // the d-part.
    cudaLaunchConfig_t cfg = {};
    cfg.gridDim  = dim3(4 * (NQ / APPLY_THREADS), 1, 1);
    cfg.blockDim = dim3(APPLY_THREADS, 1, 1);
    cfg.dynamicSmemBytes = 0;
    cfg.stream = 0;                                  // legacy default stream (captured)
    cudaLaunchAttribute attr[1];
    attr[0].id = cudaLaunchAttributeProgrammaticStreamSerialization;
    attr[0].val.programmaticStreamSerializationAllowed = 1;
    cfg.attrs = attr;
    cfg.numAttrs = 1;
    cudaLaunchKernelEx(&cfg, apply_k, mask, gr, rm, (float*)d_out);
}